// round 9
// baseline (speedup 1.0000x reference)
#include <cuda_runtime.h>
#include <cuda_fp16.h>
#include <cstdint>

#define BATCH 4096
#define IN_C 1024
#define OUT_C 1024
#define KDIM 8192   // IN_C * 8

// Scratch (static device globals — allocation-free per harness rules)
static __device__ __align__(1024) __half g_coef[(size_t)OUT_C * KDIM];  // 16 MB
static __device__ __align__(1024) float  g_u[(size_t)BATCH * IN_C];     // 16 MB

__device__ __forceinline__ uint32_t smem_u32(const void* p) {
    uint32_t a;
    asm("{ .reg .u64 t; cvta.to.shared.u64 t, %1; cvt.u32.u64 %0, t; }"
        : "=r"(a) : "l"(p));
    return a;
}
__device__ __forceinline__ float tanhap(float z) {
    float r;
    asm("tanh.approx.f32 %0, %1;" : "=f"(r) : "f"(z));
    return r;
}

// ---------------------------------------------------------------------------
// Kernel 1: u[b,i] = alpha[i]*x[b,i] + beta[i]   (fp32, 16MB)
// ---------------------------------------------------------------------------
__global__ void k_prep(const float* __restrict__ x, const float* __restrict__ alpha,
                       const float* __restrict__ beta) {
    int t = blockIdx.x * blockDim.x + threadIdx.x;   // per float4
    int i4 = t & (IN_C / 4 - 1);
    float4 xv = reinterpret_cast<const float4*>(x)[t];
    float4 a = reinterpret_cast<const float4*>(alpha)[i4];
    float4 b = reinterpret_cast<const float4*>(beta)[i4];
    float4 u;
    u.x = fmaf(a.x, xv.x, b.x);
    u.y = fmaf(a.y, xv.y, b.y);
    u.z = fmaf(a.z, xv.z, b.z);
    u.w = fmaf(a.w, xv.w, b.w);
    reinterpret_cast<float4*>(g_u)[t] = u;
}

// ---------------------------------------------------------------------------
// Kernel 2: coeffs fp32 -> fp16 (layout [o, i*8+m] is already K-major)
// ---------------------------------------------------------------------------
__global__ void k_conv(const float* __restrict__ c) {
    int idx = blockIdx.x * blockDim.x + threadIdx.x;  // per 4 floats
    float4 v = reinterpret_cast<const float4*>(c)[idx];
    union { __half2 h2[2]; uint2 u; } o;
    o.h2[0] = __floats2half2_rn(v.x, v.y);
    o.h2[1] = __floats2half2_rn(v.z, v.w);
    reinterpret_cast<uint2*>(g_coef)[idx] = o.u;
}

// ---------------------------------------------------------------------------
// Kernel 3: fused basis + HMMA fp16 GEMM  y = basis(u) @ coef^T
// A tile (basis) computed in-kernel: basis = 0.5 + 0.5*tanh(s*u - s*c),
// with s and -s*c tables resident in smem. mma.sync m16n8k16, BM=128, BN=256,
// BK=64, 16 warps (64x32 warp tiles), 3-stage pipeline. Grid 4x32 = one wave.
// ---------------------------------------------------------------------------
#define BM 128
#define BN 256
#define BK 64
#define STAGES 3
#define NTHR 512
#define NCHUNK (KDIM / BK)          // 128

#define A_BYTES (BM * 128)          // 16 KB  (128B row = 64 fp16 = BK)
#define B_BYTES (BN * 128)          // 32 KB
#define U_BYTES (BM * 8 * 4)        // 4 KB (u slice: 128 rows x 8 inputs fp32)
#define STG_BYTES (A_BYTES + B_BYTES + U_BYTES)    // 53248
#define ST_OFF 0                     // slopes table, 32 KB
#define QT_OFF 32768                 // -slope*center table, 32 KB
#define STAGES_OFF 65536
#define SM_TOTAL (STAGES_OFF + STAGES * STG_BYTES) // 225280

__device__ __forceinline__ void cp16(uint32_t dst, const void* src) {
    asm volatile("cp.async.cg.shared.global [%0], [%1], 16;" :: "r"(dst), "l"(src));
}
__device__ __forceinline__ void ldm_x4(uint32_t& r0, uint32_t& r1, uint32_t& r2, uint32_t& r3, uint32_t addr) {
    asm volatile("ldmatrix.sync.aligned.m8n8.x4.shared.b16 {%0,%1,%2,%3}, [%4];"
                 : "=r"(r0), "=r"(r1), "=r"(r2), "=r"(r3) : "r"(addr));
}
__device__ __forceinline__ void mma16816(float* d, const uint32_t* a, const uint32_t* b) {
    asm volatile("mma.sync.aligned.m16n8k16.row.col.f32.f16.f16.f32 "
                 "{%0,%1,%2,%3}, {%4,%5,%6,%7}, {%8,%9}, {%0,%1,%2,%3};"
                 : "+f"(d[0]), "+f"(d[1]), "+f"(d[2]), "+f"(d[3])
                 : "r"(a[0]), "r"(a[1]), "r"(a[2]), "r"(a[3]), "r"(b[0]), "r"(b[1]));
}

// Load B tile + u slice for one chunk into stage s.
__device__ __forceinline__ void load_stage(uint32_t sb, int stage,
                                           const __half* Bg, const float* Ug,
                                           int chunk, int tid) {
    uint32_t base = sb + STAGES_OFF + stage * STG_BYTES;
    uint32_t sB = base + A_BYTES;
    uint32_t sU = base + A_BYTES + B_BYTES;
    const char* gB = (const char*)Bg + (size_t)chunk * (BK * 2);
#pragma unroll
    for (int j = 0; j < (B_BYTES / 16) / NTHR; j++) {   // 4 iters
        int seg = tid + j * NTHR;
        uint32_t row = (uint32_t)seg >> 3;
        uint32_t off = row * 128u + ((((uint32_t)seg & 7u) * 16u) ^ ((row & 7u) << 4));
        cp16(sB + off, gB + (size_t)row * (KDIM * 2) + (size_t)((seg & 7) << 4));
    }
    if (tid < 256) {                                    // u slice: 256 x 16B
        int row = tid >> 1, half = tid & 1;
        cp16(sU + (uint32_t)tid * 16u,
             (const char*)Ug + (size_t)row * (IN_C * 4) + (size_t)chunk * 32 + half * 16);
    }
}

// Compute basis for chunk c into the A region of its stage (STS, swizzled).
__device__ __forceinline__ void compute_basis(uint32_t sb, int stage, int c, int tid) {
    uint32_t base = sb + STAGES_OFF + stage * STG_BYTES;
    uint32_t sU = base + A_BYTES + B_BYTES;
#pragma unroll
    for (int j = 0; j < 2; j++) {
        int P = tid + j * NTHR;          // 0..1023: b = P>>3, i_local = P&7
        int b = P >> 3, il = P & 7;
        float u;
        asm("ld.shared.f32 %0, [%1];" : "=f"(u) : "r"(sU + (uint32_t)P * 4u));
        uint32_t tofs = (uint32_t)(c * 64 + il * 8) * 4u;   // table offset (floats j = c*64+il*8+m)
        float4 S0, S1, Q0, Q1;
        asm("ld.shared.v4.f32 {%0,%1,%2,%3}, [%4];"
            : "=f"(S0.x), "=f"(S0.y), "=f"(S0.z), "=f"(S0.w) : "r"(sb + ST_OFF + tofs));
        asm("ld.shared.v4.f32 {%0,%1,%2,%3}, [%4];"
            : "=f"(S1.x), "=f"(S1.y), "=f"(S1.z), "=f"(S1.w) : "r"(sb + ST_OFF + tofs + 16u));
        asm("ld.shared.v4.f32 {%0,%1,%2,%3}, [%4];"
            : "=f"(Q0.x), "=f"(Q0.y), "=f"(Q0.z), "=f"(Q0.w) : "r"(sb + QT_OFF + tofs));
        asm("ld.shared.v4.f32 {%0,%1,%2,%3}, [%4];"
            : "=f"(Q1.x), "=f"(Q1.y), "=f"(Q1.z), "=f"(Q1.w) : "r"(sb + QT_OFF + tofs + 16u));
        float v[8];
        v[0] = fmaf(tanhap(fmaf(S0.x, u, Q0.x)), 0.5f, 0.5f);
        v[1] = fmaf(tanhap(fmaf(S0.y, u, Q0.y)), 0.5f, 0.5f);
        v[2] = fmaf(tanhap(fmaf(S0.z, u, Q0.z)), 0.5f, 0.5f);
        v[3] = fmaf(tanhap(fmaf(S0.w, u, Q0.w)), 0.5f, 0.5f);
        v[4] = fmaf(tanhap(fmaf(S1.x, u, Q1.x)), 0.5f, 0.5f);
        v[5] = fmaf(tanhap(fmaf(S1.y, u, Q1.y)), 0.5f, 0.5f);
        v[6] = fmaf(tanhap(fmaf(S1.z, u, Q1.z)), 0.5f, 0.5f);
        v[7] = fmaf(tanhap(fmaf(S1.w, u, Q1.w)), 0.5f, 0.5f);
        uint32_t h[4];
        __half2 t0 = __floats2half2_rn(v[0], v[1]); h[0] = *reinterpret_cast<uint32_t*>(&t0);
        __half2 t1 = __floats2half2_rn(v[2], v[3]); h[1] = *reinterpret_cast<uint32_t*>(&t1);
        __half2 t2 = __floats2half2_rn(v[4], v[5]); h[2] = *reinterpret_cast<uint32_t*>(&t2);
        __half2 t3 = __floats2half2_rn(v[6], v[7]); h[3] = *reinterpret_cast<uint32_t*>(&t3);
        uint32_t dst = base + (uint32_t)b * 128u + (((uint32_t)il * 16u) ^ (((uint32_t)b & 7u) << 4));
        asm volatile("st.shared.v4.b32 [%0], {%1,%2,%3,%4};"
                     :: "r"(dst), "r"(h[0]), "r"(h[1]), "r"(h[2]), "r"(h[3]));
    }
}

__global__ void __launch_bounds__(NTHR, 1)
k_gemm(float* __restrict__ y, const float* __restrict__ slopes,
       const float* __restrict__ centers) {
    extern __shared__ char smem[];
    uint32_t sb = smem_u32(smem);
    int tid = threadIdx.x;
    int wid = tid >> 5, lid = tid & 31;
    int tn = blockIdx.x, tm = blockIdx.y;
    const __half* Bg = g_coef + (size_t)tn * BN * KDIM;
    const float* Ug = g_u + (size_t)tm * BM * IN_C;

    int wm = wid >> 3;          // 0..1 -> warp rows wm*64
    int wn = wid & 7;           // 0..7 -> warp cols wn*32

    uint32_t aRow[4], aXor[4];
#pragma unroll
    for (int mt = 0; mt < 4; mt++) {
        aRow[mt] = (uint32_t)(wm * 64 + mt * 16 + (lid & 15));
        aXor[mt] = (aRow[mt] & 7u) << 4;
    }
    uint32_t aCol = (uint32_t)((lid >> 4) * 16);

    uint32_t bRow[2], bXor[2];
#pragma unroll
    for (int p = 0; p < 2; p++) {
        bRow[p] = (uint32_t)(wn * 32 + p * 16 + ((lid >> 4) << 3) + (lid & 7));
        bXor[p] = (bRow[p] & 7u) << 4;
    }
    uint32_t bCol = (uint32_t)(((lid >> 3) & 1) * 16);

    float acc[4][4][4];
#pragma unroll
    for (int mt = 0; mt < 4; mt++)
#pragma unroll
        for (int nt = 0; nt < 4; nt++)
#pragma unroll
            for (int q = 0; q < 4; q++) acc[mt][nt][q] = 0.0f;

    // Prologue: tables (slopes -> ST, centers -> QT) + stages 0,1
    {
#pragma unroll
        for (int j = 0; j < 4; j++) {   // 2048 cp16 per table / 512 thr
            int seg = tid + j * NTHR;
            cp16(sb + ST_OFF + (uint32_t)seg * 16u, (const char*)slopes + (size_t)seg * 16);
            cp16(sb + QT_OFF + (uint32_t)seg * 16u, (const char*)centers + (size_t)seg * 16);
        }
        load_stage(sb, 0, Bg, Ug, 0, tid);
        asm volatile("cp.async.commit_group;" ::: "memory");
        load_stage(sb, 1, Bg, Ug, 1, tid);
        asm volatile("cp.async.commit_group;" ::: "memory");
        asm volatile("cp.async.wait_group 1;" ::: "memory");
        __syncthreads();
        // QT <- -S * C  (so z = fma(S, u, QT))
#pragma unroll
        for (int j = 0; j < 4; j++) {
            uint32_t ofs = (uint32_t)(tid + j * NTHR) * 16u;
            float4 S, C;
            asm("ld.shared.v4.f32 {%0,%1,%2,%3}, [%4];"
                : "=f"(S.x), "=f"(S.y), "=f"(S.z), "=f"(S.w) : "r"(sb + ST_OFF + ofs));
            asm("ld.shared.v4.f32 {%0,%1,%2,%3}, [%4];"
                : "=f"(C.x), "=f"(C.y), "=f"(C.z), "=f"(C.w) : "r"(sb + QT_OFF + ofs));
            C.x = -S.x * C.x; C.y = -S.y * C.y; C.z = -S.z * C.z; C.w = -S.w * C.w;
            asm volatile("st.shared.v4.f32 [%0], {%1,%2,%3,%4};"
                         :: "r"(sb + QT_OFF + ofs), "f"(C.x), "f"(C.y), "f"(C.z), "f"(C.w));
        }
        __syncthreads();
        compute_basis(sb, 0, 0, tid);
        __syncthreads();
    }

    uint32_t afr[2][4][4];
    uint32_t bfr[2][2][4];

#pragma unroll 1
    for (int c = 0; c < NCHUNK; c++) {
        uint32_t base = sb + STAGES_OFF + (uint32_t)(c % STAGES) * STG_BYTES;
        uint32_t sA = base;
        uint32_t sB = base + A_BYTES;

        // kk = 0 fragments into buf 0
#pragma unroll
        for (int mt = 0; mt < 4; mt++)
            ldm_x4(afr[0][mt][0], afr[0][mt][1], afr[0][mt][2], afr[0][mt][3],
                   sA + aRow[mt] * 128u + (aCol ^ aXor[mt]));
#pragma unroll
        for (int p = 0; p < 2; p++)
            ldm_x4(bfr[0][p][0], bfr[0][p][1], bfr[0][p][2], bfr[0][p][3],
                   sB + bRow[p] * 128u + (bCol ^ bXor[p]));

#pragma unroll
        for (int kk = 0; kk < 4; kk++) {
            int cur = kk & 1, nxt = cur ^ 1;
            if (kk < 3) {
                uint32_t koff = (uint32_t)(kk + 1) * 32u;
#pragma unroll
                for (int mt = 0; mt < 4; mt++)
                    ldm_x4(afr[nxt][mt][0], afr[nxt][mt][1], afr[nxt][mt][2], afr[nxt][mt][3],
                           sA + aRow[mt] * 128u + ((koff + aCol) ^ aXor[mt]));
#pragma unroll
                for (int p = 0; p < 2; p++)
                    ldm_x4(bfr[nxt][p][0], bfr[nxt][p][1], bfr[nxt][p][2], bfr[nxt][p][3],
                           sB + bRow[p] * 128u + ((koff + bCol) ^ bXor[p]));
            }
#pragma unroll
            for (int mt = 0; mt < 4; mt++)
#pragma unroll
                for (int p = 0; p < 2; p++) {
                    mma16816(acc[mt][2 * p + 0], afr[cur][mt], &bfr[cur][p][0]);
                    mma16816(acc[mt][2 * p + 1], afr[cur][mt], &bfr[cur][p][2]);
                }
        }

        // Prefetch chunk c+2 into stage (c+2)%3 (== (c-1)%3, safe: its reads
        // finished at iter c-1, separated by the barrier at end of iter c-1).
        if (c + 2 < NCHUNK) {
            load_stage(sb, (c + 2) % STAGES, Bg, Ug, c + 2, tid);
            asm volatile("cp.async.commit_group;" ::: "memory");
        } else {
            asm volatile("cp.async.commit_group;" ::: "memory");  // keep group count uniform
        }
        // Wait for chunk c+1's B/u (issued 2 iters ago), compute its basis.
        asm volatile("cp.async.wait_group 1;" ::: "memory");
        if (c + 1 < NCHUNK) compute_basis(sb, (c + 1) % STAGES, c + 1, tid);
        __syncthreads();
    }

    // Epilogue: direct float2 stores
    int r0 = wm * 64 + (lid >> 2);
    int cb = wn * 32 + (lid & 3) * 2;
#pragma unroll
    for (int mt = 0; mt < 4; mt++) {
#pragma unroll
        for (int nt = 0; nt < 4; nt++) {
            int row = tm * BM + r0 + mt * 16;
            int col = tn * BN + cb + nt * 8;
            float2 v0 = make_float2(acc[mt][nt][0], acc[mt][nt][1]);
            float2 v1 = make_float2(acc[mt][nt][2], acc[mt][nt][3]);
            *reinterpret_cast<float2*>(y + (size_t)row * OUT_C + col) = v0;
            *reinterpret_cast<float2*>(y + (size_t)(row + 8) * OUT_C + col) = v1;
        }
    }
}

// ---------------------------------------------------------------------------
extern "C" void kernel_launch(void* const* d_in, const int* in_sizes, int n_in,
                              void* d_out, int out_size) {
    (void)in_sizes; (void)n_in; (void)out_size;
    const float* x       = (const float*)d_in[0];
    const float* coeffs  = (const float*)d_in[1];
    const float* centers = (const float*)d_in[2];
    const float* slopes  = (const float*)d_in[3];
    const float* alpha   = (const float*)d_in[4];
    const float* beta    = (const float*)d_in[5];
    float* y = (float*)d_out;

    k_prep<<<(BATCH * IN_C / 4) / 256, 256>>>(x, alpha, beta);
    k_conv<<<(OUT_C * KDIM / 4) / 256, 256>>>(coeffs);
    cudaFuncSetAttribute(k_gemm, cudaFuncAttributeMaxDynamicSharedMemorySize, SM_TOTAL);
    k_gemm<<<dim3(OUT_C / BN, BATCH / BM), NTHR, SM_TOTAL>>>(y, slopes, centers);
}

// round 12
// speedup vs baseline: 1.1069x; 1.1069x over previous
#include <cuda_runtime.h>
#include <cuda_fp16.h>
#include <cstdint>

#define BATCH 4096
#define IN_C 1024
#define OUT_C 1024
#define KDIM 8192   // IN_C * 8

// Scratch (static device globals — allocation-free per harness rules)
static __device__ __align__(1024) __half g_basis[(size_t)BATCH * KDIM]; // 64 MB
static __device__ __align__(1024) __half g_coef[(size_t)OUT_C * KDIM];  // 16 MB
static __device__ __align__(1024) float  g_E[IN_C * 8];                 // exp(2*s*c) table

__device__ __forceinline__ uint32_t smem_u32(const void* p) {
    uint32_t a;
    asm("{ .reg .u64 t; cvta.to.shared.u64 t, %1; cvt.u32.u64 %0, t; }"
        : "=r"(a) : "l"(p));
    return a;
}

// ---------------------------------------------------------------------------
// Kernel 0: E[i,m] = exp(2*slope*center)   (8192 values)
// ---------------------------------------------------------------------------
__global__ void k_etab(const float* __restrict__ centers, const float* __restrict__ slopes) {
    int j = blockIdx.x * blockDim.x + threadIdx.x;
    g_E[j] = __expf(2.0f * slopes[j] * centers[j]);
}

// ---------------------------------------------------------------------------
// Kernel 1: basis[b, i*8+m] = sigmoid(2*slope*(u - c)),  u = alpha*x + beta
// Factored: e_m = exp(-2*s*u) * E[i,m]  (slopes uniform across m per spec)
// ---------------------------------------------------------------------------
__global__ void k_basis(const float* __restrict__ x, const float* __restrict__ slopes,
                        const float* __restrict__ alpha, const float* __restrict__ beta) {
    int idx = blockIdx.x * blockDim.x + threadIdx.x;  // b * IN_C + i
    int i = idx & (IN_C - 1);
    float u = fmaf(alpha[i], x[idx], beta[i]);
    float s = slopes[8 * i];
    float t = __expf(-2.0f * s * u);
    float4 e0 = reinterpret_cast<const float4*>(g_E)[2 * i];
    float4 e1 = reinterpret_cast<const float4*>(g_E)[2 * i + 1];
    float ee[8] = {e0.x, e0.y, e0.z, e0.w, e1.x, e1.y, e1.z, e1.w};
    union { __half h[8]; uint4 v; } out;
#pragma unroll
    for (int m = 0; m < 8; m++) {
        float e = t * ee[m];                 // overflow->inf->sig 0; underflow->0->sig 1 (both correct)
        out.h[m] = __float2half_rn(__fdividef(1.0f, 1.0f + e));
    }
    reinterpret_cast<uint4*>(g_basis)[idx] = out.v;
}

// ---------------------------------------------------------------------------
// Kernel 2: coeffs fp32 -> fp16 (layout [o, i*8+m] is already K-major)
// ---------------------------------------------------------------------------
__global__ void k_conv(const float* __restrict__ c) {
    int idx = blockIdx.x * blockDim.x + threadIdx.x;  // per 4 floats
    float4 v = reinterpret_cast<const float4*>(c)[idx];
    union { __half2 h2[2]; uint2 u; } o;
    o.h2[0] = __floats2half2_rn(v.x, v.y);
    o.h2[1] = __floats2half2_rn(v.z, v.w);
    reinterpret_cast<uint2*>(g_coef)[idx] = o.u;
}

// ---------------------------------------------------------------------------
// Kernel 3: HMMA fp16 GEMM  y[4096,1024] = basis @ coef^T
// mma.sync m16n8k16, BM=128, BN=256, BK=64, 64x64 warp tiles (8 warps),
// 4-stage cp.async pipeline, XOR-swizzled smem + ldmatrix.x4,
// fragment double-buffering across k-steps. Grid 4x32 = 128 CTAs, one wave.
// ---------------------------------------------------------------------------
#define BM 128
#define BN 256
#define BK 64
#define STAGES 4
#define NTHR 256
#define NCHUNK (KDIM / BK)          // 128

#define A_BYTES (BM * 128)          // 16 KB  (128B row = 64 fp16 = BK)
#define B_BYTES (BN * 128)          // 32 KB
#define STG_BYTES (A_BYTES + B_BYTES)      // 48 KB
#define SM_TOTAL (STAGES * STG_BYTES)      // 192 KB

__device__ __forceinline__ void cp16(uint32_t dst, const void* src) {
    asm volatile("cp.async.cg.shared.global [%0], [%1], 16;" :: "r"(dst), "l"(src));
}
__device__ __forceinline__ void ldm_x4(uint32_t& r0, uint32_t& r1, uint32_t& r2, uint32_t& r3, uint32_t addr) {
    asm volatile("ldmatrix.sync.aligned.m8n8.x4.shared.b16 {%0,%1,%2,%3}, [%4];"
                 : "=r"(r0), "=r"(r1), "=r"(r2), "=r"(r3) : "r"(addr));
}
__device__ __forceinline__ void mma16816(float* d, const uint32_t* a, const uint32_t* b) {
    asm volatile("mma.sync.aligned.m16n8k16.row.col.f32.f16.f16.f32 "
                 "{%0,%1,%2,%3}, {%4,%5,%6,%7}, {%8,%9}, {%0,%1,%2,%3};"
                 : "+f"(d[0]), "+f"(d[1]), "+f"(d[2]), "+f"(d[3])
                 : "r"(a[0]), "r"(a[1]), "r"(a[2]), "r"(a[3]), "r"(b[0]), "r"(b[1]));
}

// Smem tile layout: row r x 128 bytes; physical = r*128 + (c16*16 ^ ((r&7)<<4))
__device__ __forceinline__ void load_stage(uint32_t sb, int stage,
                                           const __half* Ag, const __half* Bg,
                                           int chunk, int tid) {
    uint32_t sA = sb + stage * STG_BYTES;
    uint32_t sB = sA + A_BYTES;
    const char* gA = (const char*)Ag + (size_t)chunk * (BK * 2);
    const char* gB = (const char*)Bg + (size_t)chunk * (BK * 2);
#pragma unroll
    for (int j = 0; j < (A_BYTES / 16) / NTHR; j++) {   // 4 iters
        int seg = tid + j * NTHR;                       // row = seg>>3, c16 = seg&7
        uint32_t row = (uint32_t)seg >> 3;
        uint32_t off = row * 128u + ((((uint32_t)seg & 7u) * 16u) ^ ((row & 7u) << 4));
        cp16(sA + off, gA + (size_t)row * (KDIM * 2) + (size_t)((seg & 7) << 4));
    }
#pragma unroll
    for (int j = 0; j < (B_BYTES / 16) / NTHR; j++) {   // 8 iters
        int seg = tid + j * NTHR;
        uint32_t row = (uint32_t)seg >> 3;
        uint32_t off = row * 128u + ((((uint32_t)seg & 7u) * 16u) ^ ((row & 7u) << 4));
        cp16(sB + off, gB + (size_t)row * (KDIM * 2) + (size_t)((seg & 7) << 4));
    }
}

__global__ void __launch_bounds__(NTHR, 1)
k_gemm(float* __restrict__ y) {
    extern __shared__ char smem[];
    uint32_t sb = smem_u32(smem);
    int tid = threadIdx.x;
    int wid = tid >> 5, lid = tid & 31;
    int tn = blockIdx.x, tm = blockIdx.y;
    const __half* Ag = g_basis + (size_t)tm * BM * KDIM;
    const __half* Bg = g_coef + (size_t)tn * BN * KDIM;

    int wm = wid >> 2;          // 0..1 -> warp rows wm*64
    int wn = wid & 3;           // 0..3 -> warp cols wn*64

    // A fragments: mt 0..3 (m16 each)
    uint32_t aRow[4], aXor[4];
#pragma unroll
    for (int mt = 0; mt < 4; mt++) {
        aRow[mt] = (uint32_t)(wm * 64 + mt * 16 + (lid & 15));
        aXor[mt] = (aRow[mt] & 7u) << 4;
    }
    uint32_t aCol = (uint32_t)((lid >> 4) * 16);

    // B fragments: p 0..3 (n16 each -> two n8 tiles)
    uint32_t bRow[4], bXor[4];
#pragma unroll
    for (int p = 0; p < 4; p++) {
        bRow[p] = (uint32_t)(wn * 64 + p * 16 + ((lid >> 4) << 3) + (lid & 7));
        bXor[p] = (bRow[p] & 7u) << 4;
    }
    uint32_t bCol = (uint32_t)(((lid >> 3) & 1) * 16);

    float acc[4][8][4];
#pragma unroll
    for (int mt = 0; mt < 4; mt++)
#pragma unroll
        for (int nt = 0; nt < 8; nt++)
#pragma unroll
            for (int q = 0; q < 4; q++) acc[mt][nt][q] = 0.0f;

    // Prologue: stages 0..STAGES-2
#pragma unroll
    for (int s = 0; s < STAGES - 1; s++) {
        load_stage(sb, s, Ag, Bg, s, tid);
        asm volatile("cp.async.commit_group;" ::: "memory");
    }

    uint32_t afr[2][4][4];   // [buf][mt][4]
    uint32_t bfr[2][4][4];   // [buf][p][4]

#pragma unroll 1
    for (int c = 0; c < NCHUNK; c++) {
        asm volatile("cp.async.wait_group %0;" :: "n"(STAGES - 2) : "memory");
        __syncthreads();
        // Refill stage used by chunk c-1 (all warps finished it before this barrier)
        int nc = c + STAGES - 1;
        if (nc < NCHUNK) load_stage(sb, nc % STAGES, Ag, Bg, nc, tid);
        asm volatile("cp.async.commit_group;" ::: "memory");

        uint32_t sA = sb + (uint32_t)(c % STAGES) * STG_BYTES;
        uint32_t sB = sA + A_BYTES;

        // kk = 0 fragments into buf 0
#pragma unroll
        for (int mt = 0; mt < 4; mt++)
            ldm_x4(afr[0][mt][0], afr[0][mt][1], afr[0][mt][2], afr[0][mt][3],
                   sA + aRow[mt] * 128u + (aCol ^ aXor[mt]));
#pragma unroll
        for (int p = 0; p < 4; p++)
            ldm_x4(bfr[0][p][0], bfr[0][p][1], bfr[0][p][2], bfr[0][p][3],
                   sB + bRow[p] * 128u + (bCol ^ bXor[p]));

#pragma unroll
        for (int kk = 0; kk < 4; kk++) {
            int cur = kk & 1, nxt = cur ^ 1;
            if (kk < 3) {
                uint32_t koff = (uint32_t)(kk + 1) * 32u;
#pragma unroll
                for (int mt = 0; mt < 4; mt++)
                    ldm_x4(afr[nxt][mt][0], afr[nxt][mt][1], afr[nxt][mt][2], afr[nxt][mt][3],
                           sA + aRow[mt] * 128u + ((koff + aCol) ^ aXor[mt]));
#pragma unroll
                for (int p = 0; p < 4; p++)
                    ldm_x4(bfr[nxt][p][0], bfr[nxt][p][1], bfr[nxt][p][2], bfr[nxt][p][3],
                           sB + bRow[p] * 128u + ((koff + bCol) ^ bXor[p]));
            }
#pragma unroll
            for (int mt = 0; mt < 4; mt++)
#pragma unroll
                for (int p = 0; p < 4; p++) {
                    mma16816(acc[mt][2 * p + 0], afr[cur][mt], &bfr[cur][p][0]);
                    mma16816(acc[mt][2 * p + 1], afr[cur][mt], &bfr[cur][p][2]);
                }
        }
    }
    asm volatile("cp.async.wait_group 0;" ::: "memory");

    // Epilogue: direct float2 stores
    int r0 = wm * 64 + (lid >> 2);
    int cb = wn * 64 + (lid & 3) * 2;
#pragma unroll
    for (int mt = 0; mt < 4; mt++) {
#pragma unroll
        for (int nt = 0; nt < 8; nt++) {
            int row = tm * BM + r0 + mt * 16;
            int col = tn * BN + cb + nt * 8;
            float2 v0 = make_float2(acc[mt][nt][0], acc[mt][nt][1]);
            float2 v1 = make_float2(acc[mt][nt][2], acc[mt][nt][3]);
            *reinterpret_cast<float2*>(y + (size_t)row * OUT_C + col) = v0;
            *reinterpret_cast<float2*>(y + (size_t)(row + 8) * OUT_C + col) = v1;
        }
    }
}

// ---------------------------------------------------------------------------
extern "C" void kernel_launch(void* const* d_in, const int* in_sizes, int n_in,
                              void* d_out, int out_size) {
    (void)in_sizes; (void)n_in; (void)out_size;
    const float* x       = (const float*)d_in[0];
    const float* coeffs  = (const float*)d_in[1];
    const float* centers = (const float*)d_in[2];
    const float* slopes  = (const float*)d_in[3];
    const float* alpha   = (const float*)d_in[4];
    const float* beta    = (const float*)d_in[5];
    float* y = (float*)d_out;

    k_etab<<<(IN_C * 8) / 256, 256>>>(centers, slopes);
    k_basis<<<(BATCH * IN_C) / 256, 256>>>(x, slopes, alpha, beta);
    k_conv<<<(OUT_C * KDIM / 4) / 256, 256>>>(coeffs);
    cudaFuncSetAttribute(k_gemm, cudaFuncAttributeMaxDynamicSharedMemorySize, SM_TOTAL);
    k_gemm<<<dim3(OUT_C / BN, BATCH / BM), NTHR, SM_TOTAL>>>(y);
}